// round 16
// baseline (speedup 1.0000x reference)
#include <cuda_runtime.h>
#include <math.h>
#include <stdint.h>

// Problem constants
#define NNODES 100000
#define NEDGES 1600000
#define ETOT   (NEDGES + NNODES)   // edges + self loops
#define KDIM   256
#define LD1    128                 // HEADS*HID = 4*32
#define LD2    160                 // HEADS2*NCLASS = 4*40
#define LDCAT  256
#define NEG_SLOPE 0.2f

// ---------------- scratch (static device globals; no allocations) --------
__device__ __align__(16) float g_bufA[(size_t)NNODES * LD2];   // h1_0 then h2
__device__ __align__(16) float g_bufB[(size_t)NNODES * LD1];   // h1_1
__device__ __align__(16) float g_xcat[(size_t)NNODES * LDCAT]; // concat(elu out1_0, elu out1_1)
__device__ __align__(16) float g_pas0[NNODES * 4];
__device__ __align__(16) float g_pad0[NNODES * 4];
__device__ __align__(16) float g_pas1[NNODES * 4];
__device__ __align__(16) float g_pad1[NNODES * 4];
__device__ int g_cnt[NNODES];
__device__ int g_incl[NNODES];
__device__ int g_bsum[128];
__device__ int g_rowptr[NNODES + 1];
__device__ int g_cursor[NNODES];
__device__ int g_colidx[ETOT];

// ---------------- helpers ----------------
__device__ __forceinline__ float lrelu(float x) { return fmaxf(x, NEG_SLOPE * x); }
__device__ __forceinline__ float eluf(float x)  { return x > 0.0f ? x : expm1f(x); }

// ---------------- CSR build ----------------
__global__ void k_init_cnt(int* cnt) {
    int i = blockIdx.x * blockDim.x + threadIdx.x;
    if (i < NNODES) cnt[i] = 1;   // self-loop
}

__global__ void k_hist(const int* __restrict__ dst, int* cnt) {
    int e = blockIdx.x * blockDim.x + threadIdx.x;
    if (e < NEDGES) atomicAdd(&cnt[dst[e]], 1);
}

__global__ void k_scan1(const int* __restrict__ cnt, int* incl, int* bsum) {
    __shared__ int sh[1024];
    int i = blockIdx.x * 1024 + threadIdx.x;
    int v = (i < NNODES) ? cnt[i] : 0;
    sh[threadIdx.x] = v;
    __syncthreads();
    for (int off = 1; off < 1024; off <<= 1) {
        int t = (threadIdx.x >= off) ? sh[threadIdx.x - off] : 0;
        __syncthreads();
        sh[threadIdx.x] += t;
        __syncthreads();
    }
    if (i < NNODES) incl[i] = sh[threadIdx.x];
    if (threadIdx.x == 1023) bsum[blockIdx.x] = sh[1023];
}

#define NB_SCAN ((NNODES + 1023) / 1024)   // 98

// fused: every block redundantly scans the 98 block sums, then finalizes rowptr
__global__ void k_scan23(const int* __restrict__ incl, const int* __restrict__ bsum,
                         const int* __restrict__ cnt, int* rowptr, int* cursor) {
    __shared__ int sb[128];
    int t = threadIdx.x;
    if (t < 128) sb[t] = (t < NB_SCAN) ? bsum[t] : 0;
    __syncthreads();
    for (int off = 1; off < 128; off <<= 1) {
        int v = (t >= off && t < 128) ? sb[t - off] : 0;
        __syncthreads();
        if (t < 128) sb[t] += v;
        __syncthreads();
    }
    int i = blockIdx.x * blockDim.x + t;
    if (i >= NNODES) return;
    int blk = i >> 10;
    int off = blk ? sb[blk - 1] : 0;
    int inc = incl[i] + off;
    int start = inc - cnt[i];
    rowptr[i] = start;
    cursor[i] = start;
    if (i == NNODES - 1) rowptr[NNODES] = inc;
}

__global__ void k_scatter(const int* __restrict__ src, const int* __restrict__ dst,
                          int* cursor, int* colidx) {
    int e = blockIdx.x * blockDim.x + threadIdx.x;
    if (e < NEDGES) {
        int d = dst[e];
        int p = atomicAdd(&cursor[d], 1);
        colidx[p] = src[e];
    } else if (e < ETOT) {
        int n = e - NEDGES;
        int p = atomicAdd(&cursor[n], 1);
        colidx[p] = n;
    }
}

// ================= 3xTF32 tensor-core GEMM (fp32-accurate) =================
// Templated on NT = n-tiles per warp (warp tile N = NT*8, block N = 2*NT*8).
#define GBM 128
#define GBK 16

__device__ __forceinline__ void cpasync16(void* dst, const void* src, bool pred) {
    uint32_t d = (uint32_t)__cvta_generic_to_shared(dst);
    int sz = pred ? 16 : 0;
    asm volatile("cp.async.cg.shared.global [%0], [%1], 16, %2;\n"
                 :: "r"(d), "l"(src), "r"(sz));
}
__device__ __forceinline__ void cp_commit() {
    asm volatile("cp.async.commit_group;\n");
}
template <int NWAIT>
__device__ __forceinline__ void cp_wait() {
    asm volatile("cp.async.wait_group %0;\n" :: "n"(NWAIT));
}

__device__ __forceinline__ uint32_t f2tf32(float x) {
    uint32_t r;
    asm("cvt.rna.tf32.f32 %0, %1;\n" : "=r"(r) : "f"(x));
    return r;
}
__device__ __forceinline__ void split_tf32(float x, uint32_t& hi, uint32_t& lo) {
    hi = f2tf32(x);
    lo = f2tf32(x - __uint_as_float(hi));
}

__device__ __forceinline__ void mma_tf32(float* c, const uint32_t* a, const uint32_t* b) {
    asm volatile(
        "mma.sync.aligned.m16n8k8.row.col.f32.tf32.tf32.f32 "
        "{%0,%1,%2,%3}, {%4,%5,%6,%7}, {%8,%9}, {%0,%1,%2,%3};\n"
        : "+f"(c[0]), "+f"(c[1]), "+f"(c[2]), "+f"(c[3])
        : "r"(a[0]), "r"(a[1]), "r"(a[2]), "r"(a[3]), "r"(b[0]), "r"(b[1]));
}

template <int NT>
struct GemmStageT {
    static const int BN = NT * 16;
    float As[GBM][GBK + 4];
    float Bs[GBK][BN + 8];
};

template <int NT>
__device__ __forceinline__ void gemm_load_stage_t(
    GemmStageT<NT>& st, const float* __restrict__ A, const float* __restrict__ B,
    int m0, int n0, int k0, int M, int Ncols, int lda, int ldb, int tid)
{
    const int BN = NT * 16;
    // A tile: 128 rows x 16 cols = 512 float4
#pragma unroll
    for (int i = tid; i < 512; i += 256) {
        int row = i >> 2;
        int q = (i & 3) * 4;
        int grow = m0 + row;
        bool p = grow < M;
        int crow = p ? grow : (M - 1);
        cpasync16(&st.As[row][q], A + (size_t)crow * lda + k0 + q, p);
    }
    // B tile: 16 rows x BN cols = 4*BN float4
#pragma unroll
    for (int i = tid; i < 4 * BN; i += 256) {
        int row = i / (BN / 4);
        int c = (i % (BN / 4)) * 4;
        bool p = (n0 + c) < Ncols;
        int cc = p ? (n0 + c) : 0;
        cpasync16(&st.Bs[row][c], B + (size_t)(k0 + row) * ldb + cc, p);
    }
    cp_commit();
}

// If batched (gridDim.z == 2), blockIdx.z == 1 selects the (A2,B2,C2) triple.
template <int NT>
__global__ void __launch_bounds__(256, 2) k_gemm_3xtf32(
    const float* __restrict__ A, const float* __restrict__ B, float* __restrict__ C,
    const float* __restrict__ A2, const float* __restrict__ B2, float* __restrict__ C2,
    int M, int K, int Ncols, int lda, int ldb, int ldc, int n_base)
{
    __shared__ GemmStageT<NT> stg[2];
    const int BN = NT * 16;

    if (blockIdx.z == 1) { A = A2; B = B2; C = C2; }

    int tid  = threadIdx.x;
    int warp = tid >> 5, lane = tid & 31;
    int wm = warp >> 1, wn = warp & 1;
    int g = lane >> 2, tq = lane & 3;

    int m0 = blockIdx.x * GBM;
    int n0 = n_base + blockIdx.y * BN;

    float acc[2][NT][4];
#pragma unroll
    for (int mt = 0; mt < 2; mt++)
#pragma unroll
        for (int nt = 0; nt < NT; nt++)
#pragma unroll
            for (int r = 0; r < 4; r++) acc[mt][nt][r] = 0.0f;

    int nit = K / GBK;
    gemm_load_stage_t<NT>(stg[0], A, B, m0, n0, 0, M, Ncols, lda, ldb, tid);

    for (int it = 0; it < nit; it++) {
        if (it + 1 < nit) {
            gemm_load_stage_t<NT>(stg[(it + 1) & 1], A, B, m0, n0, (it + 1) * GBK,
                                  M, Ncols, lda, ldb, tid);
            cp_wait<1>();
        } else {
            cp_wait<0>();
        }
        __syncthreads();

        GemmStageT<NT>& s = stg[it & 1];
#pragma unroll
        for (int kk = 0; kk < GBK; kk += 8) {
            uint32_t ahi[2][4], alo[2][4];
#pragma unroll
            for (int mt = 0; mt < 2; mt++) {
                int mb = wm * 32 + mt * 16;
                split_tf32(s.As[mb + g][kk + tq],          ahi[mt][0], alo[mt][0]);
                split_tf32(s.As[mb + 8 + g][kk + tq],      ahi[mt][1], alo[mt][1]);
                split_tf32(s.As[mb + g][kk + tq + 4],      ahi[mt][2], alo[mt][2]);
                split_tf32(s.As[mb + 8 + g][kk + tq + 4],  ahi[mt][3], alo[mt][3]);
            }
            uint32_t bhi[NT][2], blo[NT][2];
#pragma unroll
            for (int nt = 0; nt < NT; nt++) {
                int nb = wn * (NT * 8) + nt * 8 + g;
                split_tf32(s.Bs[kk + tq][nb],     bhi[nt][0], blo[nt][0]);
                split_tf32(s.Bs[kk + tq + 4][nb], bhi[nt][1], blo[nt][1]);
            }
#pragma unroll
            for (int mt = 0; mt < 2; mt++)
#pragma unroll
                for (int nt = 0; nt < NT; nt++) {
                    mma_tf32(acc[mt][nt], alo[mt], bhi[nt]);
                    mma_tf32(acc[mt][nt], ahi[mt], blo[nt]);
                    mma_tf32(acc[mt][nt], ahi[mt], bhi[nt]);
                }
        }
        __syncthreads();
    }

#pragma unroll
    for (int mt = 0; mt < 2; mt++) {
        int row0 = m0 + wm * 32 + mt * 16 + g;
        int row1 = row0 + 8;
#pragma unroll
        for (int nt = 0; nt < NT; nt++) {
            int col = n0 + wn * (NT * 8) + nt * 8 + tq * 2;
            if (col < Ncols) {
                if (row0 < M)
                    *(float2*)(C + (size_t)row0 * ldc + col) =
                        make_float2(acc[mt][nt][0], acc[mt][nt][1]);
                if (row1 < M)
                    *(float2*)(C + (size_t)row1 * ldc + col) =
                        make_float2(acc[mt][nt][2], acc[mt][nt][3]);
            }
        }
    }
}

// ---------------- per-node attention coefficients (warp per node) ----------------
__global__ void k_alpha(const float* __restrict__ htab, int ld, int cdim,
                        const float* __restrict__ asrc, const float* __restrict__ adst,
                        float* __restrict__ out_s, float* __restrict__ out_d)
{
    int warp = (blockIdx.x * blockDim.x + threadIdx.x) >> 5;
    int lane = threadIdx.x & 31;
    if (warp >= NNODES) return;
    const float* hrow = htab + (size_t)warp * ld;
#pragma unroll
    for (int h = 0; h < 4; h++) {
        float s = 0.f, d = 0.f;
        for (int c = lane; c < cdim; c += 32) {
            float v = hrow[h * cdim + c];
            s += v * asrc[h * cdim + c];
            d += v * adst[h * cdim + c];
        }
#pragma unroll
        for (int o = 16; o; o >>= 1) {
            s += __shfl_xor_sync(0xffffffffu, s, o);
            d += __shfl_xor_sync(0xffffffffu, d, o);
        }
        if (lane == 0) {
            out_s[warp * 4 + h] = s;
            out_d[warp * 4 + h] = d;
        }
    }
}

// ------- fused layer-1 aggregation for both GAT branches (one colidx pass) -------
__global__ void k_agg1_dual(
    const float* __restrict__ tabA, const float* __restrict__ asA,
    const float* __restrict__ adA, const float* __restrict__ biasA,
    const float* __restrict__ tabB, const float* __restrict__ asB,
    const float* __restrict__ adB, const float* __restrict__ biasB,
    const int* __restrict__ rowptr, const int* __restrict__ colidx,
    float* __restrict__ out)
{
    int n = (blockIdx.x * blockDim.x + threadIdx.x) >> 5;
    int lane = threadIdx.x & 31;
    if (n >= NNODES) return;
    int s0 = rowptr[n], s1 = rowptr[n + 1];
    float4 adA4 = ((const float4*)adA)[n];
    float4 adB4 = ((const float4*)adB)[n];
    int head = lane >> 3;

    float4 accA = make_float4(0.f, 0.f, 0.f, 0.f);
    float4 accB = make_float4(0.f, 0.f, 0.f, 0.f);
    float4 dacA = make_float4(0.f, 0.f, 0.f, 0.f);
    float4 dacB = make_float4(0.f, 0.f, 0.f, 0.f);

    for (int base = s0; base < s1; base += 32) {
        int i = base + lane;
        int src = 0;
        float4 wa = make_float4(0.f, 0.f, 0.f, 0.f);
        float4 wb = make_float4(0.f, 0.f, 0.f, 0.f);
        if (i < s1) {
            src = colidx[i];
            float4 aA = ((const float4*)asA)[src];
            float4 aB = ((const float4*)asB)[src];
            wa.x = __expf(lrelu(aA.x + adA4.x));
            wa.y = __expf(lrelu(aA.y + adA4.y));
            wa.z = __expf(lrelu(aA.z + adA4.z));
            wa.w = __expf(lrelu(aA.w + adA4.w));
            wb.x = __expf(lrelu(aB.x + adB4.x));
            wb.y = __expf(lrelu(aB.y + adB4.y));
            wb.z = __expf(lrelu(aB.z + adB4.z));
            wb.w = __expf(lrelu(aB.w + adB4.w));
            dacA.x += wa.x; dacA.y += wa.y; dacA.z += wa.z; dacA.w += wa.w;
            dacB.x += wb.x; dacB.y += wb.y; dacB.z += wb.z; dacB.w += wb.w;
        }
        int cnt = min(32, s1 - base);
        int j = 0;
        for (; j + 1 < cnt; j += 2) {
            int s1i = __shfl_sync(0xffffffffu, src, j);
            int s2i = __shfl_sync(0xffffffffu, src, j + 1);
            float4 hA1 = ((const float4*)(tabA + (size_t)s1i * LD1))[lane];
            float4 hB1 = ((const float4*)(tabB + (size_t)s1i * LD1))[lane];
            float4 hA2 = ((const float4*)(tabA + (size_t)s2i * LD1))[lane];
            float4 hB2 = ((const float4*)(tabB + (size_t)s2i * LD1))[lane];
            float a0 = __shfl_sync(0xffffffffu, wa.x, j);
            float a1 = __shfl_sync(0xffffffffu, wa.y, j);
            float a2 = __shfl_sync(0xffffffffu, wa.z, j);
            float a3 = __shfl_sync(0xffffffffu, wa.w, j);
            float wA1 = head == 0 ? a0 : head == 1 ? a1 : head == 2 ? a2 : a3;
            float b0 = __shfl_sync(0xffffffffu, wb.x, j);
            float b1 = __shfl_sync(0xffffffffu, wb.y, j);
            float b2 = __shfl_sync(0xffffffffu, wb.z, j);
            float b3 = __shfl_sync(0xffffffffu, wb.w, j);
            float wB1 = head == 0 ? b0 : head == 1 ? b1 : head == 2 ? b2 : b3;
            float c0 = __shfl_sync(0xffffffffu, wa.x, j + 1);
            float c1 = __shfl_sync(0xffffffffu, wa.y, j + 1);
            float c2 = __shfl_sync(0xffffffffu, wa.z, j + 1);
            float c3 = __shfl_sync(0xffffffffu, wa.w, j + 1);
            float wA2 = head == 0 ? c0 : head == 1 ? c1 : head == 2 ? c2 : c3;
            float d0 = __shfl_sync(0xffffffffu, wb.x, j + 1);
            float d1 = __shfl_sync(0xffffffffu, wb.y, j + 1);
            float d2 = __shfl_sync(0xffffffffu, wb.z, j + 1);
            float d3 = __shfl_sync(0xffffffffu, wb.w, j + 1);
            float wB2 = head == 0 ? d0 : head == 1 ? d1 : head == 2 ? d2 : d3;
            accA.x += wA1 * hA1.x + wA2 * hA2.x;
            accA.y += wA1 * hA1.y + wA2 * hA2.y;
            accA.z += wA1 * hA1.z + wA2 * hA2.z;
            accA.w += wA1 * hA1.w + wA2 * hA2.w;
            accB.x += wB1 * hB1.x + wB2 * hB2.x;
            accB.y += wB1 * hB1.y + wB2 * hB2.y;
            accB.z += wB1 * hB1.z + wB2 * hB2.z;
            accB.w += wB1 * hB1.w + wB2 * hB2.w;
        }
        if (j < cnt) {
            int s1i = __shfl_sync(0xffffffffu, src, j);
            float4 hA1 = ((const float4*)(tabA + (size_t)s1i * LD1))[lane];
            float4 hB1 = ((const float4*)(tabB + (size_t)s1i * LD1))[lane];
            float a0 = __shfl_sync(0xffffffffu, wa.x, j);
            float a1 = __shfl_sync(0xffffffffu, wa.y, j);
            float a2 = __shfl_sync(0xffffffffu, wa.z, j);
            float a3 = __shfl_sync(0xffffffffu, wa.w, j);
            float wA1 = head == 0 ? a0 : head == 1 ? a1 : head == 2 ? a2 : a3;
            float b0 = __shfl_sync(0xffffffffu, wb.x, j);
            float b1 = __shfl_sync(0xffffffffu, wb.y, j);
            float b2 = __shfl_sync(0xffffffffu, wb.z, j);
            float b3 = __shfl_sync(0xffffffffu, wb.w, j);
            float wB1 = head == 0 ? b0 : head == 1 ? b1 : head == 2 ? b2 : b3;
            accA.x += wA1 * hA1.x; accA.y += wA1 * hA1.y;
            accA.z += wA1 * hA1.z; accA.w += wA1 * hA1.w;
            accB.x += wB1 * hB1.x; accB.y += wB1 * hB1.y;
            accB.z += wB1 * hB1.z; accB.w += wB1 * hB1.w;
        }
    }

#pragma unroll
    for (int o = 16; o; o >>= 1) {
        dacA.x += __shfl_xor_sync(0xffffffffu, dacA.x, o);
        dacA.y += __shfl_xor_sync(0xffffffffu, dacA.y, o);
        dacA.z += __shfl_xor_sync(0xffffffffu, dacA.z, o);
        dacA.w += __shfl_xor_sync(0xffffffffu, dacA.w, o);
        dacB.x += __shfl_xor_sync(0xffffffffu, dacB.x, o);
        dacB.y += __shfl_xor_sync(0xffffffffu, dacB.y, o);
        dacB.z += __shfl_xor_sync(0xffffffffu, dacB.z, o);
        dacB.w += __shfl_xor_sync(0xffffffffu, dacB.w, o);
    }
    float dA = head == 0 ? dacA.x : head == 1 ? dacA.y : head == 2 ? dacA.z : dacA.w;
    float dB = head == 0 ? dacB.x : head == 1 ? dacB.y : head == 2 ? dacB.z : dacB.w;
    float invA = 1.f / (dA + 1e-16f);
    float invB = 1.f / (dB + 1e-16f);
    float4 bA = ((const float4*)biasA)[lane];
    float4 bB = ((const float4*)biasB)[lane];
    float4 oA, oB;
    oA.x = eluf(accA.x * invA + bA.x);
    oA.y = eluf(accA.y * invA + bA.y);
    oA.z = eluf(accA.z * invA + bA.z);
    oA.w = eluf(accA.w * invA + bA.w);
    oB.x = eluf(accB.x * invB + bB.x);
    oB.y = eluf(accB.y * invB + bB.y);
    oB.z = eluf(accB.z * invB + bB.z);
    oB.w = eluf(accB.w * invB + bB.w);
    ((float4*)(out + (size_t)n * LDCAT))[lane] = oA;
    ((float4*)(out + (size_t)n * LDCAT + 128))[lane] = oB;
}

// ---------------- layer-2 aggregation: float4 gathers + shfl-transpose head-mean ------
__global__ void k_agg2(const float* __restrict__ htab, const float* __restrict__ as,
                       const float* __restrict__ ad, const float* __restrict__ bias,
                       const int* __restrict__ rowptr, const int* __restrict__ colidx,
                       float* __restrict__ out)
{
    int n = (blockIdx.x * blockDim.x + threadIdx.x) >> 5;
    int lane = threadIdx.x & 31;
    if (n >= NNODES) return;
    int s0 = rowptr[n], s1 = rowptr[n + 1];
    float4 ad4 = ((const float4*)ad)[n];
    int head1 = lane / 10;
    bool hasB = lane < 8;

    float4 acc1 = make_float4(0.f, 0.f, 0.f, 0.f);
    float4 acc2 = make_float4(0.f, 0.f, 0.f, 0.f);
    float4 dac = make_float4(0.f, 0.f, 0.f, 0.f);

    for (int base = s0; base < s1; base += 32) {
        int i = base + lane;
        int src = 0;
        float4 w4 = make_float4(0.f, 0.f, 0.f, 0.f);
        if (i < s1) {
            src = colidx[i];
            float4 a = ((const float4*)as)[src];
            w4.x = __expf(lrelu(a.x + ad4.x));
            w4.y = __expf(lrelu(a.y + ad4.y));
            w4.z = __expf(lrelu(a.z + ad4.z));
            w4.w = __expf(lrelu(a.w + ad4.w));
            dac.x += w4.x; dac.y += w4.y; dac.z += w4.z; dac.w += w4.w;
        }
        int cnt = min(32, s1 - base);
        int j = 0;
        for (; j + 1 < cnt; j += 2) {
            int sA = __shfl_sync(0xffffffffu, src, j);
            int sB = __shfl_sync(0xffffffffu, src, j + 1);
            const float4* hA = (const float4*)(htab + (size_t)sA * LD2);
            const float4* hB = (const float4*)(htab + (size_t)sB * LD2);
            float4 vA1 = hA[lane];
            float4 vB1 = hB[lane];
            float a0 = __shfl_sync(0xffffffffu, w4.x, j);
            float a1 = __shfl_sync(0xffffffffu, w4.y, j);
            float a2 = __shfl_sync(0xffffffffu, w4.z, j);
            float a3 = __shfl_sync(0xffffffffu, w4.w, j);
            float b0 = __shfl_sync(0xffffffffu, w4.x, j + 1);
            float b1 = __shfl_sync(0xffffffffu, w4.y, j + 1);
            float b2 = __shfl_sync(0xffffffffu, w4.z, j + 1);
            float b3 = __shfl_sync(0xffffffffu, w4.w, j + 1);
            float wA = head1 == 0 ? a0 : head1 == 1 ? a1 : head1 == 2 ? a2 : a3;
            float wB = head1 == 0 ? b0 : head1 == 1 ? b1 : head1 == 2 ? b2 : b3;
            acc1.x += wA * vA1.x + wB * vB1.x;
            acc1.y += wA * vA1.y + wB * vB1.y;
            acc1.z += wA * vA1.z + wB * vB1.z;
            acc1.w += wA * vA1.w + wB * vB1.w;
            if (hasB) {
                float4 vA2 = hA[32 + lane];
                float4 vB2 = hB[32 + lane];
                acc2.x += a3 * vA2.x + b3 * vB2.x;
                acc2.y += a3 * vA2.y + b3 * vB2.y;
                acc2.z += a3 * vA2.z + b3 * vB2.z;
                acc2.w += a3 * vA2.w + b3 * vB2.w;
            }
        }
        if (j < cnt) {
            int sA = __shfl_sync(0xffffffffu, src, j);
            const float4* hA = (const float4*)(htab + (size_t)sA * LD2);
            float4 vA1 = hA[lane];
            float a0 = __shfl_sync(0xffffffffu, w4.x, j);
            float a1 = __shfl_sync(0xffffffffu, w4.y, j);
            float a2 = __shfl_sync(0xffffffffu, w4.z, j);
            float a3 = __shfl_sync(0xffffffffu, w4.w, j);
            float wA = head1 == 0 ? a0 : head1 == 1 ? a1 : head1 == 2 ? a2 : a3;
            acc1.x += wA * vA1.x;
            acc1.y += wA * vA1.y;
            acc1.z += wA * vA1.z;
            acc1.w += wA * vA1.w;
            if (hasB) {
                float4 vA2 = hA[32 + lane];
                acc2.x += a3 * vA2.x;
                acc2.y += a3 * vA2.y;
                acc2.z += a3 * vA2.z;
                acc2.w += a3 * vA2.w;
            }
        }
    }

#pragma unroll
    for (int o = 16; o; o >>= 1) {
        dac.x += __shfl_xor_sync(0xffffffffu, dac.x, o);
        dac.y += __shfl_xor_sync(0xffffffffu, dac.y, o);
        dac.z += __shfl_xor_sync(0xffffffffu, dac.z, o);
        dac.w += __shfl_xor_sync(0xffffffffu, dac.w, o);
    }
    float i0 = 1.f / (dac.x + 1e-16f), i1 = 1.f / (dac.y + 1e-16f);
    float i2 = 1.f / (dac.z + 1e-16f), i3 = 1.f / (dac.w + 1e-16f);
    float invh = head1 == 0 ? i0 : head1 == 1 ? i1 : head1 == 2 ? i2 : i3;
    acc1.x *= invh; acc1.y *= invh; acc1.z *= invh; acc1.w *= invh;
    acc2.x *= i3;   acc2.y *= i3;   acc2.z *= i3;   acc2.w *= i3;

    int q = lane;
    int l1 = q + 10, l2 = q + 20;
    int l3a = 30 + q;
    int l3b = q - 2;
    float4 t1, t2, u, v;
    t1.x = __shfl_sync(0xffffffffu, acc1.x, l1);
    t1.y = __shfl_sync(0xffffffffu, acc1.y, l1);
    t1.z = __shfl_sync(0xffffffffu, acc1.z, l1);
    t1.w = __shfl_sync(0xffffffffu, acc1.w, l1);
    t2.x = __shfl_sync(0xffffffffu, acc1.x, l2);
    t2.y = __shfl_sync(0xffffffffu, acc1.y, l2);
    t2.z = __shfl_sync(0xffffffffu, acc1.z, l2);
    t2.w = __shfl_sync(0xffffffffu, acc1.w, l2);
    u.x = __shfl_sync(0xffffffffu, acc1.x, l3a);
    u.y = __shfl_sync(0xffffffffu, acc1.y, l3a);
    u.z = __shfl_sync(0xffffffffu, acc1.z, l3a);
    u.w = __shfl_sync(0xffffffffu, acc1.w, l3a);
    v.x = __shfl_sync(0xffffffffu, acc2.x, l3b & 31);
    v.y = __shfl_sync(0xffffffffu, acc2.y, l3b & 31);
    v.z = __shfl_sync(0xffffffffu, acc2.z, l3b & 31);
    v.w = __shfl_sync(0xffffffffu, acc2.w, l3b & 31);
    if (q < 10) {
        float4 t3 = (q < 2) ? u : v;
        float4 b4 = ((const float4*)bias)[q];
        float4 o4;
        o4.x = 0.25f * (acc1.x + t1.x + t2.x + t3.x) + b4.x;
        o4.y = 0.25f * (acc1.y + t1.y + t2.y + t3.y) + b4.y;
        o4.z = 0.25f * (acc1.z + t1.z + t2.z + t3.z) + b4.z;
        o4.w = 0.25f * (acc1.w + t1.w + t2.w + t3.w) + b4.w;
        ((float4*)(out + (size_t)n * 40))[q] = o4;
    }
}

// ---------------- launch ----------------
extern "C" void kernel_launch(void* const* d_in, const int* in_sizes, int n_in,
                              void* d_out, int out_size)
{
    const float* x0    = (const float*)d_in[0];
    const float* x1    = (const float*)d_in[1];
    const int*   ei    = (const int*)d_in[2];
    const float* W1_0  = (const float*)d_in[3];
    const float* aS1_0 = (const float*)d_in[4];
    const float* aD1_0 = (const float*)d_in[5];
    const float* b1_0  = (const float*)d_in[6];
    const float* W1_1  = (const float*)d_in[7];
    const float* aS1_1 = (const float*)d_in[8];
    const float* aD1_1 = (const float*)d_in[9];
    const float* b1_1  = (const float*)d_in[10];
    const float* W2    = (const float*)d_in[11];
    const float* aS2   = (const float*)d_in[12];
    const float* aD2   = (const float*)d_in[13];
    const float* b2    = (const float*)d_in[14];
    float* out = (float*)d_out;

    const int* srcp = ei;
    const int* dstp = ei + NEDGES;

    float *bufA, *bufB, *xcat, *pas0, *pad0, *pas1, *pad1;
    int *cnt, *incl, *bsum, *rowptr, *cursor, *colidx;
    cudaGetSymbolAddress((void**)&bufA, g_bufA);
    cudaGetSymbolAddress((void**)&bufB, g_bufB);
    cudaGetSymbolAddress((void**)&xcat, g_xcat);
    cudaGetSymbolAddress((void**)&pas0, g_pas0);
    cudaGetSymbolAddress((void**)&pad0, g_pad0);
    cudaGetSymbolAddress((void**)&pas1, g_pas1);
    cudaGetSymbolAddress((void**)&pad1, g_pad1);
    cudaGetSymbolAddress((void**)&cnt, g_cnt);
    cudaGetSymbolAddress((void**)&incl, g_incl);
    cudaGetSymbolAddress((void**)&bsum, g_bsum);
    cudaGetSymbolAddress((void**)&rowptr, g_rowptr);
    cudaGetSymbolAddress((void**)&cursor, g_cursor);
    cudaGetSymbolAddress((void**)&colidx, g_colidx);

    dim3 blk(256);
    int gm = (NNODES + GBM - 1) / GBM;   // 782

    // CSR build interleaved so the layer-1 batched GEMM is the 4th launch
    k_init_cnt<<<(NNODES + 255) / 256, 256>>>(cnt);
    k_hist<<<(NEDGES + 255) / 256, 256>>>(dstp, cnt);
    k_scan1<<<NB_SCAN, 1024>>>(cnt, incl, bsum);

    // both layer-1 GEMMs in one z-batched launch
    k_gemm_3xtf32<8><<<dim3(gm, 1, 2), blk>>>(
        x0, W1_0, bufA, x1, W1_1, bufB,
        NNODES, KDIM, LD1, KDIM, LD1, LD1, 0);

    k_scan23<<<(NNODES + 255) / 256, 256>>>(incl, bsum, cnt, rowptr, cursor);
    k_scatter<<<(ETOT + 255) / 256, 256>>>(srcp, dstp, cursor, colidx);

    // attention coefficients
    k_alpha<<<12500, 256>>>(bufA, LD1, 32, aS1_0, aD1_0, pas0, pad0);
    k_alpha<<<12500, 256>>>(bufB, LD1, 32, aS1_1, aD1_1, pas1, pad1);
    // fused layer-1 aggregation for both branches (+bias +ELU) -> concat buffer
    k_agg1_dual<<<12500, 256>>>(bufA, pas0, pad0, b1_0,
                                bufB, pas1, pad1, b1_1,
                                rowptr, colidx, xcat);
    // layer-2 GEMM: main 128 cols (NT=8) + 32-col tail (NT=2)
    k_gemm_3xtf32<8><<<dim3(gm, 1, 1), blk>>>(
        xcat, W2, bufA, xcat, W2, bufA,
        NNODES, KDIM, LD2, LDCAT, LD2, LD2, 0);
    k_gemm_3xtf32<2><<<dim3(gm, 1, 1), blk>>>(
        xcat, W2, bufA, xcat, W2, bufA,
        NNODES, KDIM, LD2, LDCAT, LD2, LD2, 128);
    k_alpha<<<12500, 256>>>(bufA, LD2, 40, aS2, aD2, pas0, pad0);
    // layer-2 aggregation: head mean + bias -> d_out
    k_agg2<<<12500, 256>>>(bufA, pas0, pad0, b2, rowptr, colidx, out);
}

// round 17
// speedup vs baseline: 1.4681x; 1.4681x over previous
#include <cuda_runtime.h>
#include <math.h>
#include <stdint.h>

// Problem constants
#define NNODES 100000
#define NEDGES 1600000
#define ETOT   (NEDGES + NNODES)   // edges + self loops
#define KDIM   256
#define LD1    128                 // HEADS*HID = 4*32
#define LD2    160                 // HEADS2*NCLASS = 4*40
#define LDCAT  256
#define NEG_SLOPE 0.2f

// ---------------- scratch (static device globals; no allocations) --------
__device__ __align__(16) float g_bufA[(size_t)NNODES * LD2];   // h1_0 then h2
__device__ __align__(16) float g_bufB[(size_t)NNODES * LD1];   // h1_1
__device__ __align__(16) float g_xcat[(size_t)NNODES * LDCAT]; // concat(elu out1_0, elu out1_1)
__device__ __align__(16) float g_pas0[NNODES * 4];
__device__ __align__(16) float g_pad0[NNODES * 4];
__device__ __align__(16) float g_pas1[NNODES * 4];
__device__ __align__(16) float g_pad1[NNODES * 4];
__device__ int g_cnt[NNODES];
__device__ int g_incl[NNODES];
__device__ int g_bsum[128];
__device__ int g_rowptr[NNODES + 1];
__device__ int g_cursor[NNODES];
__device__ int g_colidx[ETOT];

// ---------------- helpers ----------------
__device__ __forceinline__ float lrelu(float x) { return fmaxf(x, NEG_SLOPE * x); }
__device__ __forceinline__ float eluf(float x)  { return x > 0.0f ? x : expm1f(x); }

// ---------------- CSR build ----------------
__global__ void k_init_cnt(int* cnt) {
    int i = blockIdx.x * blockDim.x + threadIdx.x;
    if (i < NNODES) cnt[i] = 1;   // self-loop
}

__global__ void k_hist(const int* __restrict__ dst, int* cnt) {
    int e = blockIdx.x * blockDim.x + threadIdx.x;
    if (e < NEDGES) atomicAdd(&cnt[dst[e]], 1);
}

__global__ void k_scan1(const int* __restrict__ cnt, int* incl, int* bsum) {
    __shared__ int sh[1024];
    int i = blockIdx.x * 1024 + threadIdx.x;
    int v = (i < NNODES) ? cnt[i] : 0;
    sh[threadIdx.x] = v;
    __syncthreads();
    for (int off = 1; off < 1024; off <<= 1) {
        int t = (threadIdx.x >= off) ? sh[threadIdx.x - off] : 0;
        __syncthreads();
        sh[threadIdx.x] += t;
        __syncthreads();
    }
    if (i < NNODES) incl[i] = sh[threadIdx.x];
    if (threadIdx.x == 1023) bsum[blockIdx.x] = sh[1023];
}

#define NB_SCAN ((NNODES + 1023) / 1024)   // 98

// fused: every block redundantly scans the 98 block sums, then finalizes rowptr
__global__ void k_scan23(const int* __restrict__ incl, const int* __restrict__ bsum,
                         const int* __restrict__ cnt, int* rowptr, int* cursor) {
    __shared__ int sb[128];
    int t = threadIdx.x;
    if (t < 128) sb[t] = (t < NB_SCAN) ? bsum[t] : 0;
    __syncthreads();
    for (int off = 1; off < 128; off <<= 1) {
        int v = (t >= off && t < 128) ? sb[t - off] : 0;
        __syncthreads();
        if (t < 128) sb[t] += v;
        __syncthreads();
    }
    int i = blockIdx.x * blockDim.x + t;
    if (i >= NNODES) return;
    int blk = i >> 10;
    int off = blk ? sb[blk - 1] : 0;
    int inc = incl[i] + off;
    int start = inc - cnt[i];
    rowptr[i] = start;
    cursor[i] = start;
    if (i == NNODES - 1) rowptr[NNODES] = inc;
}

__global__ void k_scatter(const int* __restrict__ src, const int* __restrict__ dst,
                          int* cursor, int* colidx) {
    int e = blockIdx.x * blockDim.x + threadIdx.x;
    if (e < NEDGES) {
        int d = dst[e];
        int p = atomicAdd(&cursor[d], 1);
        colidx[p] = src[e];
    } else if (e < ETOT) {
        int n = e - NEDGES;
        int p = atomicAdd(&cursor[n], 1);
        colidx[p] = n;
    }
}

// ================= 3xTF32 tensor-core GEMM (fp32-accurate) =================
// Templated on NT = n-tiles per warp (warp tile N = NT*8, block N = 2*NT*8).
#define GBM 128
#define GBK 16

__device__ __forceinline__ void cpasync16(void* dst, const void* src, bool pred) {
    uint32_t d = (uint32_t)__cvta_generic_to_shared(dst);
    int sz = pred ? 16 : 0;
    asm volatile("cp.async.cg.shared.global [%0], [%1], 16, %2;\n"
                 :: "r"(d), "l"(src), "r"(sz));
}
__device__ __forceinline__ void cp_commit() {
    asm volatile("cp.async.commit_group;\n");
}
template <int NWAIT>
__device__ __forceinline__ void cp_wait() {
    asm volatile("cp.async.wait_group %0;\n" :: "n"(NWAIT));
}

__device__ __forceinline__ uint32_t f2tf32(float x) {
    uint32_t r;
    asm("cvt.rna.tf32.f32 %0, %1;\n" : "=r"(r) : "f"(x));
    return r;
}
__device__ __forceinline__ void split_tf32(float x, uint32_t& hi, uint32_t& lo) {
    hi = f2tf32(x);
    lo = f2tf32(x - __uint_as_float(hi));
}

__device__ __forceinline__ void mma_tf32(float* c, const uint32_t* a, const uint32_t* b) {
    asm volatile(
        "mma.sync.aligned.m16n8k8.row.col.f32.tf32.tf32.f32 "
        "{%0,%1,%2,%3}, {%4,%5,%6,%7}, {%8,%9}, {%0,%1,%2,%3};\n"
        : "+f"(c[0]), "+f"(c[1]), "+f"(c[2]), "+f"(c[3])
        : "r"(a[0]), "r"(a[1]), "r"(a[2]), "r"(a[3]), "r"(b[0]), "r"(b[1]));
}

template <int NT>
struct GemmStageT {
    static const int BN = NT * 16;
    float As[GBM][GBK + 4];
    float Bs[GBK][BN + 8];
};

template <int NT>
__device__ __forceinline__ void gemm_load_stage_t(
    GemmStageT<NT>& st, const float* __restrict__ A, const float* __restrict__ B,
    int m0, int n0, int k0, int M, int Ncols, int lda, int ldb, int tid)
{
    const int BN = NT * 16;
    // A tile: 128 rows x 16 cols = 512 float4
#pragma unroll
    for (int i = tid; i < 512; i += 256) {
        int row = i >> 2;
        int q = (i & 3) * 4;
        int grow = m0 + row;
        bool p = grow < M;
        int crow = p ? grow : (M - 1);
        cpasync16(&st.As[row][q], A + (size_t)crow * lda + k0 + q, p);
    }
    // B tile: 16 rows x BN cols = 4*BN float4
#pragma unroll
    for (int i = tid; i < 4 * BN; i += 256) {
        int row = i / (BN / 4);
        int c = (i % (BN / 4)) * 4;
        bool p = (n0 + c) < Ncols;
        int cc = p ? (n0 + c) : 0;
        cpasync16(&st.Bs[row][c], B + (size_t)(k0 + row) * ldb + cc, p);
    }
    cp_commit();
}

// If batched (gridDim.z == 2), blockIdx.z == 1 selects the (A2,B2,C2) triple.
template <int NT>
__global__ void __launch_bounds__(256, 2) k_gemm_3xtf32(
    const float* __restrict__ A, const float* __restrict__ B, float* __restrict__ C,
    const float* __restrict__ A2, const float* __restrict__ B2, float* __restrict__ C2,
    int M, int K, int Ncols, int lda, int ldb, int ldc, int n_base)
{
    __shared__ GemmStageT<NT> stg[2];
    const int BN = NT * 16;

    if (blockIdx.z == 1) { A = A2; B = B2; C = C2; }

    int tid  = threadIdx.x;
    int warp = tid >> 5, lane = tid & 31;
    int wm = warp >> 1, wn = warp & 1;
    int g = lane >> 2, tq = lane & 3;

    int m0 = blockIdx.x * GBM;
    int n0 = n_base + blockIdx.y * BN;

    float acc[2][NT][4];
#pragma unroll
    for (int mt = 0; mt < 2; mt++)
#pragma unroll
        for (int nt = 0; nt < NT; nt++)
#pragma unroll
            for (int r = 0; r < 4; r++) acc[mt][nt][r] = 0.0f;

    int nit = K / GBK;
    gemm_load_stage_t<NT>(stg[0], A, B, m0, n0, 0, M, Ncols, lda, ldb, tid);

    for (int it = 0; it < nit; it++) {
        if (it + 1 < nit) {
            gemm_load_stage_t<NT>(stg[(it + 1) & 1], A, B, m0, n0, (it + 1) * GBK,
                                  M, Ncols, lda, ldb, tid);
            cp_wait<1>();
        } else {
            cp_wait<0>();
        }
        __syncthreads();

        GemmStageT<NT>& s = stg[it & 1];
#pragma unroll
        for (int kk = 0; kk < GBK; kk += 8) {
            uint32_t ahi[2][4], alo[2][4];
#pragma unroll
            for (int mt = 0; mt < 2; mt++) {
                int mb = wm * 32 + mt * 16;
                split_tf32(s.As[mb + g][kk + tq],          ahi[mt][0], alo[mt][0]);
                split_tf32(s.As[mb + 8 + g][kk + tq],      ahi[mt][1], alo[mt][1]);
                split_tf32(s.As[mb + g][kk + tq + 4],      ahi[mt][2], alo[mt][2]);
                split_tf32(s.As[mb + 8 + g][kk + tq + 4],  ahi[mt][3], alo[mt][3]);
            }
            uint32_t bhi[NT][2], blo[NT][2];
#pragma unroll
            for (int nt = 0; nt < NT; nt++) {
                int nb = wn * (NT * 8) + nt * 8 + g;
                split_tf32(s.Bs[kk + tq][nb],     bhi[nt][0], blo[nt][0]);
                split_tf32(s.Bs[kk + tq + 4][nb], bhi[nt][1], blo[nt][1]);
            }
#pragma unroll
            for (int mt = 0; mt < 2; mt++)
#pragma unroll
                for (int nt = 0; nt < NT; nt++) {
                    mma_tf32(acc[mt][nt], alo[mt], bhi[nt]);
                    mma_tf32(acc[mt][nt], ahi[mt], blo[nt]);
                    mma_tf32(acc[mt][nt], ahi[mt], bhi[nt]);
                }
        }
        __syncthreads();
    }

#pragma unroll
    for (int mt = 0; mt < 2; mt++) {
        int row0 = m0 + wm * 32 + mt * 16 + g;
        int row1 = row0 + 8;
#pragma unroll
        for (int nt = 0; nt < NT; nt++) {
            int col = n0 + wn * (NT * 8) + nt * 8 + tq * 2;
            if (col < Ncols) {
                if (row0 < M)
                    *(float2*)(C + (size_t)row0 * ldc + col) =
                        make_float2(acc[mt][nt][0], acc[mt][nt][1]);
                if (row1 < M)
                    *(float2*)(C + (size_t)row1 * ldc + col) =
                        make_float2(acc[mt][nt][2], acc[mt][nt][3]);
            }
        }
    }
}

// ---------------- per-node attention coefficients (warp per node) ----------------
__global__ void k_alpha(const float* __restrict__ htab, int ld, int cdim,
                        const float* __restrict__ asrc, const float* __restrict__ adst,
                        float* __restrict__ out_s, float* __restrict__ out_d)
{
    int warp = (blockIdx.x * blockDim.x + threadIdx.x) >> 5;
    int lane = threadIdx.x & 31;
    if (warp >= NNODES) return;
    const float* hrow = htab + (size_t)warp * ld;
#pragma unroll
    for (int h = 0; h < 4; h++) {
        float s = 0.f, d = 0.f;
        for (int c = lane; c < cdim; c += 32) {
            float v = hrow[h * cdim + c];
            s += v * asrc[h * cdim + c];
            d += v * adst[h * cdim + c];
        }
#pragma unroll
        for (int o = 16; o; o >>= 1) {
            s += __shfl_xor_sync(0xffffffffu, s, o);
            d += __shfl_xor_sync(0xffffffffu, d, o);
        }
        if (lane == 0) {
            out_s[warp * 4 + h] = s;
            out_d[warp * 4 + h] = d;
        }
    }
}

// ------- fused layer-1 aggregation for both GAT branches (one colidx pass) -------
__global__ void k_agg1_dual(
    const float* __restrict__ tabA, const float* __restrict__ asA,
    const float* __restrict__ adA, const float* __restrict__ biasA,
    const float* __restrict__ tabB, const float* __restrict__ asB,
    const float* __restrict__ adB, const float* __restrict__ biasB,
    const int* __restrict__ rowptr, const int* __restrict__ colidx,
    float* __restrict__ out)
{
    int n = (blockIdx.x * blockDim.x + threadIdx.x) >> 5;
    int lane = threadIdx.x & 31;
    if (n >= NNODES) return;
    int s0 = rowptr[n], s1 = rowptr[n + 1];
    float4 adA4 = ((const float4*)adA)[n];
    float4 adB4 = ((const float4*)adB)[n];
    int head = lane >> 3;

    float4 accA = make_float4(0.f, 0.f, 0.f, 0.f);
    float4 accB = make_float4(0.f, 0.f, 0.f, 0.f);
    float4 dacA = make_float4(0.f, 0.f, 0.f, 0.f);
    float4 dacB = make_float4(0.f, 0.f, 0.f, 0.f);

    for (int base = s0; base < s1; base += 32) {
        int i = base + lane;
        int src = 0;
        float4 wa = make_float4(0.f, 0.f, 0.f, 0.f);
        float4 wb = make_float4(0.f, 0.f, 0.f, 0.f);
        if (i < s1) {
            src = colidx[i];
            float4 aA = ((const float4*)asA)[src];
            float4 aB = ((const float4*)asB)[src];
            wa.x = __expf(lrelu(aA.x + adA4.x));
            wa.y = __expf(lrelu(aA.y + adA4.y));
            wa.z = __expf(lrelu(aA.z + adA4.z));
            wa.w = __expf(lrelu(aA.w + adA4.w));
            wb.x = __expf(lrelu(aB.x + adB4.x));
            wb.y = __expf(lrelu(aB.y + adB4.y));
            wb.z = __expf(lrelu(aB.z + adB4.z));
            wb.w = __expf(lrelu(aB.w + adB4.w));
            dacA.x += wa.x; dacA.y += wa.y; dacA.z += wa.z; dacA.w += wa.w;
            dacB.x += wb.x; dacB.y += wb.y; dacB.z += wb.z; dacB.w += wb.w;
        }
        int cnt = min(32, s1 - base);
        int j = 0;
        for (; j + 1 < cnt; j += 2) {
            int s1i = __shfl_sync(0xffffffffu, src, j);
            int s2i = __shfl_sync(0xffffffffu, src, j + 1);
            float4 hA1 = ((const float4*)(tabA + (size_t)s1i * LD1))[lane];
            float4 hB1 = ((const float4*)(tabB + (size_t)s1i * LD1))[lane];
            float4 hA2 = ((const float4*)(tabA + (size_t)s2i * LD1))[lane];
            float4 hB2 = ((const float4*)(tabB + (size_t)s2i * LD1))[lane];
            float a0 = __shfl_sync(0xffffffffu, wa.x, j);
            float a1 = __shfl_sync(0xffffffffu, wa.y, j);
            float a2 = __shfl_sync(0xffffffffu, wa.z, j);
            float a3 = __shfl_sync(0xffffffffu, wa.w, j);
            float wA1 = head == 0 ? a0 : head == 1 ? a1 : head == 2 ? a2 : a3;
            float b0 = __shfl_sync(0xffffffffu, wb.x, j);
            float b1 = __shfl_sync(0xffffffffu, wb.y, j);
            float b2 = __shfl_sync(0xffffffffu, wb.z, j);
            float b3 = __shfl_sync(0xffffffffu, wb.w, j);
            float wB1 = head == 0 ? b0 : head == 1 ? b1 : head == 2 ? b2 : b3;
            float c0 = __shfl_sync(0xffffffffu, wa.x, j + 1);
            float c1 = __shfl_sync(0xffffffffu, wa.y, j + 1);
            float c2 = __shfl_sync(0xffffffffu, wa.z, j + 1);
            float c3 = __shfl_sync(0xffffffffu, wa.w, j + 1);
            float wA2 = head == 0 ? c0 : head == 1 ? c1 : head == 2 ? c2 : c3;
            float d0 = __shfl_sync(0xffffffffu, wb.x, j + 1);
            float d1 = __shfl_sync(0xffffffffu, wb.y, j + 1);
            float d2 = __shfl_sync(0xffffffffu, wb.z, j + 1);
            float d3 = __shfl_sync(0xffffffffu, wb.w, j + 1);
            float wB2 = head == 0 ? d0 : head == 1 ? d1 : head == 2 ? d2 : d3;
            accA.x += wA1 * hA1.x + wA2 * hA2.x;
            accA.y += wA1 * hA1.y + wA2 * hA2.y;
            accA.z += wA1 * hA1.z + wA2 * hA2.z;
            accA.w += wA1 * hA1.w + wA2 * hA2.w;
            accB.x += wB1 * hB1.x + wB2 * hB2.x;
            accB.y += wB1 * hB1.y + wB2 * hB2.y;
            accB.z += wB1 * hB1.z + wB2 * hB2.z;
            accB.w += wB1 * hB1.w + wB2 * hB2.w;
        }
        if (j < cnt) {
            int s1i = __shfl_sync(0xffffffffu, src, j);
            float4 hA1 = ((const float4*)(tabA + (size_t)s1i * LD1))[lane];
            float4 hB1 = ((const float4*)(tabB + (size_t)s1i * LD1))[lane];
            float a0 = __shfl_sync(0xffffffffu, wa.x, j);
            float a1 = __shfl_sync(0xffffffffu, wa.y, j);
            float a2 = __shfl_sync(0xffffffffu, wa.z, j);
            float a3 = __shfl_sync(0xffffffffu, wa.w, j);
            float wA1 = head == 0 ? a0 : head == 1 ? a1 : head == 2 ? a2 : a3;
            float b0 = __shfl_sync(0xffffffffu, wb.x, j);
            float b1 = __shfl_sync(0xffffffffu, wb.y, j);
            float b2 = __shfl_sync(0xffffffffu, wb.z, j);
            float b3 = __shfl_sync(0xffffffffu, wb.w, j);
            float wB1 = head == 0 ? b0 : head == 1 ? b1 : head == 2 ? b2 : b3;
            accA.x += wA1 * hA1.x; accA.y += wA1 * hA1.y;
            accA.z += wA1 * hA1.z; accA.w += wA1 * hA1.w;
            accB.x += wB1 * hB1.x; accB.y += wB1 * hB1.y;
            accB.z += wB1 * hB1.z; accB.w += wB1 * hB1.w;
        }
    }

#pragma unroll
    for (int o = 16; o; o >>= 1) {
        dacA.x += __shfl_xor_sync(0xffffffffu, dacA.x, o);
        dacA.y += __shfl_xor_sync(0xffffffffu, dacA.y, o);
        dacA.z += __shfl_xor_sync(0xffffffffu, dacA.z, o);
        dacA.w += __shfl_xor_sync(0xffffffffu, dacA.w, o);
        dacB.x += __shfl_xor_sync(0xffffffffu, dacB.x, o);
        dacB.y += __shfl_xor_sync(0xffffffffu, dacB.y, o);
        dacB.z += __shfl_xor_sync(0xffffffffu, dacB.z, o);
        dacB.w += __shfl_xor_sync(0xffffffffu, dacB.w, o);
    }
    float dA = head == 0 ? dacA.x : head == 1 ? dacA.y : head == 2 ? dacA.z : dacA.w;
    float dB = head == 0 ? dacB.x : head == 1 ? dacB.y : head == 2 ? dacB.z : dacB.w;
    float invA = 1.f / (dA + 1e-16f);
    float invB = 1.f / (dB + 1e-16f);
    float4 bA = ((const float4*)biasA)[lane];
    float4 bB = ((const float4*)biasB)[lane];
    float4 oA, oB;
    oA.x = eluf(accA.x * invA + bA.x);
    oA.y = eluf(accA.y * invA + bA.y);
    oA.z = eluf(accA.z * invA + bA.z);
    oA.w = eluf(accA.w * invA + bA.w);
    oB.x = eluf(accB.x * invB + bB.x);
    oB.y = eluf(accB.y * invB + bB.y);
    oB.z = eluf(accB.z * invB + bB.z);
    oB.w = eluf(accB.w * invB + bB.w);
    ((float4*)(out + (size_t)n * LDCAT))[lane] = oA;
    ((float4*)(out + (size_t)n * LDCAT + 128))[lane] = oB;
}

// ---------------- layer-2 aggregation: float4 gathers + shfl-transpose head-mean ------
__global__ void k_agg2(const float* __restrict__ htab, const float* __restrict__ as,
                       const float* __restrict__ ad, const float* __restrict__ bias,
                       const int* __restrict__ rowptr, const int* __restrict__ colidx,
                       float* __restrict__ out)
{
    int n = (blockIdx.x * blockDim.x + threadIdx.x) >> 5;
    int lane = threadIdx.x & 31;
    if (n >= NNODES) return;
    int s0 = rowptr[n], s1 = rowptr[n + 1];
    float4 ad4 = ((const float4*)ad)[n];
    int head1 = lane / 10;
    bool hasB = lane < 8;

    float4 acc1 = make_float4(0.f, 0.f, 0.f, 0.f);
    float4 acc2 = make_float4(0.f, 0.f, 0.f, 0.f);
    float4 dac = make_float4(0.f, 0.f, 0.f, 0.f);

    for (int base = s0; base < s1; base += 32) {
        int i = base + lane;
        int src = 0;
        float4 w4 = make_float4(0.f, 0.f, 0.f, 0.f);
        if (i < s1) {
            src = colidx[i];
            float4 a = ((const float4*)as)[src];
            w4.x = __expf(lrelu(a.x + ad4.x));
            w4.y = __expf(lrelu(a.y + ad4.y));
            w4.z = __expf(lrelu(a.z + ad4.z));
            w4.w = __expf(lrelu(a.w + ad4.w));
            dac.x += w4.x; dac.y += w4.y; dac.z += w4.z; dac.w += w4.w;
        }
        int cnt = min(32, s1 - base);
        int j = 0;
        for (; j + 1 < cnt; j += 2) {
            int sA = __shfl_sync(0xffffffffu, src, j);
            int sB = __shfl_sync(0xffffffffu, src, j + 1);
            const float4* hA = (const float4*)(htab + (size_t)sA * LD2);
            const float4* hB = (const float4*)(htab + (size_t)sB * LD2);
            float4 vA1 = hA[lane];
            float4 vB1 = hB[lane];
            float a0 = __shfl_sync(0xffffffffu, w4.x, j);
            float a1 = __shfl_sync(0xffffffffu, w4.y, j);
            float a2 = __shfl_sync(0xffffffffu, w4.z, j);
            float a3 = __shfl_sync(0xffffffffu, w4.w, j);
            float b0 = __shfl_sync(0xffffffffu, w4.x, j + 1);
            float b1 = __shfl_sync(0xffffffffu, w4.y, j + 1);
            float b2 = __shfl_sync(0xffffffffu, w4.z, j + 1);
            float b3 = __shfl_sync(0xffffffffu, w4.w, j + 1);
            float wA = head1 == 0 ? a0 : head1 == 1 ? a1 : head1 == 2 ? a2 : a3;
            float wB = head1 == 0 ? b0 : head1 == 1 ? b1 : head1 == 2 ? b2 : b3;
            acc1.x += wA * vA1.x + wB * vB1.x;
            acc1.y += wA * vA1.y + wB * vB1.y;
            acc1.z += wA * vA1.z + wB * vB1.z;
            acc1.w += wA * vA1.w + wB * vB1.w;
            if (hasB) {
                float4 vA2 = hA[32 + lane];
                float4 vB2 = hB[32 + lane];
                acc2.x += a3 * vA2.x + b3 * vB2.x;
                acc2.y += a3 * vA2.y + b3 * vB2.y;
                acc2.z += a3 * vA2.z + b3 * vB2.z;
                acc2.w += a3 * vA2.w + b3 * vB2.w;
            }
        }
        if (j < cnt) {
            int sA = __shfl_sync(0xffffffffu, src, j);
            const float4* hA = (const float4*)(htab + (size_t)sA * LD2);
            float4 vA1 = hA[lane];
            float a0 = __shfl_sync(0xffffffffu, w4.x, j);
            float a1 = __shfl_sync(0xffffffffu, w4.y, j);
            float a2 = __shfl_sync(0xffffffffu, w4.z, j);
            float a3 = __shfl_sync(0xffffffffu, w4.w, j);
            float wA = head1 == 0 ? a0 : head1 == 1 ? a1 : head1 == 2 ? a2 : a3;
            acc1.x += wA * vA1.x;
            acc1.y += wA * vA1.y;
            acc1.z += wA * vA1.z;
            acc1.w += wA * vA1.w;
            if (hasB) {
                float4 vA2 = hA[32 + lane];
                acc2.x += a3 * vA2.x;
                acc2.y += a3 * vA2.y;
                acc2.z += a3 * vA2.z;
                acc2.w += a3 * vA2.w;
            }
        }
    }

#pragma unroll
    for (int o = 16; o; o >>= 1) {
        dac.x += __shfl_xor_sync(0xffffffffu, dac.x, o);
        dac.y += __shfl_xor_sync(0xffffffffu, dac.y, o);
        dac.z += __shfl_xor_sync(0xffffffffu, dac.z, o);
        dac.w += __shfl_xor_sync(0xffffffffu, dac.w, o);
    }
    float i0 = 1.f / (dac.x + 1e-16f), i1 = 1.f / (dac.y + 1e-16f);
    float i2 = 1.f / (dac.z + 1e-16f), i3 = 1.f / (dac.w + 1e-16f);
    float invh = head1 == 0 ? i0 : head1 == 1 ? i1 : head1 == 2 ? i2 : i3;
    acc1.x *= invh; acc1.y *= invh; acc1.z *= invh; acc1.w *= invh;
    acc2.x *= i3;   acc2.y *= i3;   acc2.z *= i3;   acc2.w *= i3;

    int q = lane;
    int l1 = q + 10, l2 = q + 20;
    int l3a = 30 + q;
    int l3b = q - 2;
    float4 t1, t2, u, v;
    t1.x = __shfl_sync(0xffffffffu, acc1.x, l1);
    t1.y = __shfl_sync(0xffffffffu, acc1.y, l1);
    t1.z = __shfl_sync(0xffffffffu, acc1.z, l1);
    t1.w = __shfl_sync(0xffffffffu, acc1.w, l1);
    t2.x = __shfl_sync(0xffffffffu, acc1.x, l2);
    t2.y = __shfl_sync(0xffffffffu, acc1.y, l2);
    t2.z = __shfl_sync(0xffffffffu, acc1.z, l2);
    t2.w = __shfl_sync(0xffffffffu, acc1.w, l2);
    u.x = __shfl_sync(0xffffffffu, acc1.x, l3a);
    u.y = __shfl_sync(0xffffffffu, acc1.y, l3a);
    u.z = __shfl_sync(0xffffffffu, acc1.z, l3a);
    u.w = __shfl_sync(0xffffffffu, acc1.w, l3a);
    v.x = __shfl_sync(0xffffffffu, acc2.x, l3b & 31);
    v.y = __shfl_sync(0xffffffffu, acc2.y, l3b & 31);
    v.z = __shfl_sync(0xffffffffu, acc2.z, l3b & 31);
    v.w = __shfl_sync(0xffffffffu, acc2.w, l3b & 31);
    if (q < 10) {
        float4 t3 = (q < 2) ? u : v;
        float4 b4 = ((const float4*)bias)[q];
        float4 o4;
        o4.x = 0.25f * (acc1.x + t1.x + t2.x + t3.x) + b4.x;
        o4.y = 0.25f * (acc1.y + t1.y + t2.y + t3.y) + b4.y;
        o4.z = 0.25f * (acc1.z + t1.z + t2.z + t3.z) + b4.z;
        o4.w = 0.25f * (acc1.w + t1.w + t2.w + t3.w) + b4.w;
        ((float4*)(out + (size_t)n * 40))[q] = o4;
    }
}

// ---------------- launch ----------------
extern "C" void kernel_launch(void* const* d_in, const int* in_sizes, int n_in,
                              void* d_out, int out_size)
{
    const float* x0    = (const float*)d_in[0];
    const float* x1    = (const float*)d_in[1];
    const int*   ei    = (const int*)d_in[2];
    const float* W1_0  = (const float*)d_in[3];
    const float* aS1_0 = (const float*)d_in[4];
    const float* aD1_0 = (const float*)d_in[5];
    const float* b1_0  = (const float*)d_in[6];
    const float* W1_1  = (const float*)d_in[7];
    const float* aS1_1 = (const float*)d_in[8];
    const float* aD1_1 = (const float*)d_in[9];
    const float* b1_1  = (const float*)d_in[10];
    const float* W2    = (const float*)d_in[11];
    const float* aS2   = (const float*)d_in[12];
    const float* aD2   = (const float*)d_in[13];
    const float* b2    = (const float*)d_in[14];
    float* out = (float*)d_out;

    const int* srcp = ei;
    const int* dstp = ei + NEDGES;

    float *bufA, *bufB, *xcat, *pas0, *pad0, *pas1, *pad1;
    int *cnt, *incl, *bsum, *rowptr, *cursor, *colidx;
    cudaGetSymbolAddress((void**)&bufA, g_bufA);
    cudaGetSymbolAddress((void**)&bufB, g_bufB);
    cudaGetSymbolAddress((void**)&xcat, g_xcat);
    cudaGetSymbolAddress((void**)&pas0, g_pas0);
    cudaGetSymbolAddress((void**)&pad0, g_pad0);
    cudaGetSymbolAddress((void**)&pas1, g_pas1);
    cudaGetSymbolAddress((void**)&pad1, g_pad1);
    cudaGetSymbolAddress((void**)&cnt, g_cnt);
    cudaGetSymbolAddress((void**)&incl, g_incl);
    cudaGetSymbolAddress((void**)&bsum, g_bsum);
    cudaGetSymbolAddress((void**)&rowptr, g_rowptr);
    cudaGetSymbolAddress((void**)&cursor, g_cursor);
    cudaGetSymbolAddress((void**)&colidx, g_colidx);

    dim3 blk(256);
    int gm = (NNODES + GBM - 1) / GBM;   // 782

    // CSR build interleaved so the layer-1 batched GEMM is the 4th launch
    k_init_cnt<<<(NNODES + 255) / 256, 256>>>(cnt);
    k_hist<<<(NEDGES + 255) / 256, 256>>>(dstp, cnt);
    k_scan1<<<NB_SCAN, 1024>>>(cnt, incl, bsum);

    // both layer-1 GEMMs in one z-batched launch
    k_gemm_3xtf32<8><<<dim3(gm, 1, 2), blk>>>(
        x0, W1_0, bufA, x1, W1_1, bufB,
        NNODES, KDIM, LD1, KDIM, LD1, LD1, 0);

    k_scan23<<<(NNODES + 255) / 256, 256>>>(incl, bsum, cnt, rowptr, cursor);
    k_scatter<<<(ETOT + 255) / 256, 256>>>(srcp, dstp, cursor, colidx);

    // attention coefficients
    k_alpha<<<12500, 256>>>(bufA, LD1, 32, aS1_0, aD1_0, pas0, pad0);
    k_alpha<<<12500, 256>>>(bufB, LD1, 32, aS1_1, aD1_1, pas1, pad1);
    // fused layer-1 aggregation for both branches (+bias +ELU) -> concat buffer
    k_agg1_dual<<<12500, 256>>>(bufA, pas0, pad0, b1_0,
                                bufB, pas1, pad1, b1_1,
                                rowptr, colidx, xcat);
    // layer-2 GEMM: main 128 cols (NT=8) + 32-col tail (NT=2)
    k_gemm_3xtf32<8><<<dim3(gm, 1, 1), blk>>>(
        xcat, W2, bufA, xcat, W2, bufA,
        NNODES, KDIM, LD2, LDCAT, LD2, LD2, 0);
    k_gemm_3xtf32<2><<<dim3(gm, 1, 1), blk>>>(
        xcat, W2, bufA, xcat, W2, bufA,
        NNODES, KDIM, LD2, LDCAT, LD2, LD2, 128);
    k_alpha<<<12500, 256>>>(bufA, LD2, 40, aS2, aD2, pas0, pad0);
    // layer-2 aggregation: head mean + bias -> d_out
    k_agg2<<<12500, 256>>>(bufA, pas0, pad0, b2, rowptr, colidx, out);
}